// round 11
// baseline (speedup 1.0000x reference)
#include <cuda_runtime.h>
#include <cstdint>

// ---------------------------------------------------------------------------
// QuantizerEncoder: persistent 2-CTA/SM tf32 HMMA screen + top-2 gap;
// flagged entries compacted and exactly recomputed in fp32.
//
//   score[code][px] = sum_d Mmat[code][d] * x[d][px]
//   out[n,h,w,m] = argmax_code score  (float-coded index)
// ---------------------------------------------------------------------------

typedef unsigned long long ULL;

__device__ float g_A[262144];             // tf32-hi, m16n8k8 A-frag layout
__device__ float g_MT[4 * 128 * 256];     // fp32 M^T [m][d][k] (refine)
__device__ int   g_cnt[4];                // flagged counts per m
__device__ int   g_list[4 * 65536];       // flagged pixel lists per m

#define GAP_TH 0.05f
#define NCTA 296
#define NUNITS 2048

static __device__ __forceinline__ uint32_t f2tf32(float v) {
    uint32_t u;
    asm("cvt.rna.tf32.f32 %0, %1;" : "=r"(u) : "f"(v));
    return u;
}

static __device__ __forceinline__ uint32_t smem_u32(const void* p) {
    uint32_t a;
    asm("{ .reg .u64 t; cvta.to.shared.u64 t, %1; cvt.u32.u64 %0, t; }"
        : "=r"(a) : "l"(p));
    return a;
}

static __device__ __forceinline__ void mma8(float* d, float4 a, float2 b) {
    asm volatile(
        "mma.sync.aligned.m16n8k8.row.col.f32.tf32.tf32.f32 "
        "{%0,%1,%2,%3}, {%4,%5,%6,%7}, {%8,%9}, {%0,%1,%2,%3};"
        : "+f"(d[0]), "+f"(d[1]), "+f"(d[2]), "+f"(d[3])
        : "r"(__float_as_uint(a.x)), "r"(__float_as_uint(a.y)),
          "r"(__float_as_uint(a.z)), "r"(__float_as_uint(a.w)),
          "r"(__float_as_uint(b.x)), "r"(__float_as_uint(b.y)));
}

static __device__ __forceinline__ unsigned mono(float f) {
    unsigned u = __float_as_uint(f);
    return (u & 0x80000000u) ? ~u : (u | 0x80000000u);
}
static __device__ __forceinline__ float imono(unsigned u) {
    return (u & 0x80000000u) ? __uint_as_float(u & 0x7fffffffu)
                             : __uint_as_float(~u);
}

// ---------------- fused setup: keys (smem) -> Mmat -> g_A/g_MT --------------
__global__ __launch_bounds__(256, 1)
void setup_kernel(const float* __restrict__ cb, const float* __restrict__ wk,
                  const float* __restrict__ wq) {
    extern __shared__ float sm[];
    float* skeys = sm + 16512;   // [8 k][128 c]
    float* scb   = sm + 17536;   // [8 k][128 d]
    const int m = blockIdx.y, kch = blockIdx.x, t = threadIdx.x;

    const float4* wk4 = (const float4*)(wk + (size_t)m * 16384);
#pragma unroll
    for (int i = 0; i < 16; i++) {
        int j = i * 256 + t, c = j >> 5, d4 = j & 31;
        float4 v = __ldg(wk4 + j);
        sm[(4 * d4 + 0) * 129 + c] = v.x;
        sm[(4 * d4 + 1) * 129 + c] = v.y;
        sm[(4 * d4 + 2) * 129 + c] = v.z;
        sm[(4 * d4 + 3) * 129 + c] = v.w;
    }
    ((float4*)scb)[t] = __ldg((const float4*)(cb + ((size_t)m * 256 + kch * 8) * 128) + t);
    __syncthreads();
    {
        int c = t & 127, b = t >> 7;
        float s0 = 0.f, s1 = 0.f, s2 = 0.f, s3 = 0.f;
#pragma unroll 8
        for (int d = 0; d < 128; d++) {
            float w = sm[d * 129 + c];
            s0 += scb[(b + 0) * 128 + d] * w;
            s1 += scb[(b + 2) * 128 + d] * w;
            s2 += scb[(b + 4) * 128 + d] * w;
            s3 += scb[(b + 6) * 128 + d] * w;
        }
        skeys[(b + 0) * 128 + c] = s0;
        skeys[(b + 2) * 128 + c] = s1;
        skeys[(b + 4) * 128 + c] = s2;
        skeys[(b + 6) * 128 + c] = s3;
    }
    __syncthreads();

    const float4* wq4 = (const float4*)(wq + (size_t)m * 16384);
#pragma unroll
    for (int i = 0; i < 16; i++) ((float4*)sm)[i * 256 + t] = __ldg(wq4 + i * 256 + t);
    __syncthreads();
    {
        int d = t & 127, b = t >> 7;
        float v0 = 0.f, v1 = 0.f, v2 = 0.f, v3 = 0.f;
#pragma unroll 8
        for (int c = 0; c < 128; c++) {
            float w = sm[c * 128 + d];
            v0 += w * skeys[(b + 0) * 128 + c];
            v1 += w * skeys[(b + 2) * 128 + c];
            v2 += w * skeys[(b + 4) * 128 + c];
            v3 += w * skeys[(b + 6) * 128 + c];
        }
        float vals[4] = {v0, v1, v2, v3};
#pragma unroll
        for (int q = 0; q < 4; q++) {
            int kl = b + 2 * q;
            int k = kch * 8 + kl;
            float val = vals[q];
            g_MT[((size_t)m * 128 + d) * 256 + k] = val;

            uint32_t hib = f2tf32(val);
            int half_ = k >> 7, w = (k & 127) >> 4, r = k & 15;
            int ks = d >> 3, dc = d & 7;
            int ln, fi;
            if (r < 8) { ln = r * 4 + (dc & 3); fi = (dc >= 4) ? 2 : 0; }
            else       { ln = (r - 8) * 4 + (dc & 3); fi = (dc >= 4) ? 3 : 1; }
            size_t base = (size_t)(((m * 2 + half_) * 8 + w) * 16 + ks) * 128 + ln * 4 + fi;
            g_A[base] = __uint_as_float(hib);
        }
    }
    if (blockIdx.x == 0 && blockIdx.y == 0 && t < 4) g_cnt[t] = 0;
}

// ---------------- stage 1: persistent 1-pass tf32 + top-2 + flags -----------
// grid = 296 persistent CTAs (2/SM), 256 threads; each loops ~7 units.
// unit u = cta + i*296: m = u>>9, tile = u&511 -> 128 px.
// smem floats: [0,17408) B tf32 [128 d][136]; stage @17408 (8192f, raw hi-d);
// gkeys ULL[16][128] @17408 and gsecs u32 @21504 alias stage. 102400 B.
__global__ __launch_bounds__(256, 2)
void score_kernel(const float* __restrict__ latent, float* __restrict__ out) {
    extern __shared__ float sb[];
    float* stage = sb + 17408;
    ULL* gkeys = (ULL*)(sb + 17408);
    unsigned* gsecs = (unsigned*)(sb + 21504);

    const int t = threadIdx.x, lane = t & 31, wid = t >> 5;
    const int cta = blockIdx.x;
    const int my_units = (NUNITS - cta + NCTA - 1) / NCTA;
    const uint32_t stg = smem_u32(stage);

    for (int i = 0; i < my_units; i++) {
        const int u = cta + i * NCTA;
        const int m = u >> 9, tile = u & 511;
        const int n = tile >> 5;
        const int p0 = (tile & 31) << 7;
        const float* xb = latent + ((size_t)(n * 512 + m * 128)) * 4096 + p0;

        // async stage of hi-d half (d 64..127) raw fp32
#pragma unroll
        for (int q = 0; q < 8; q++) {
            int idx = q * 256 + t;
            int dh = idx >> 5, p4 = idx & 31;
            const float* src = xb + (size_t)(64 + dh) * 4096 + p4 * 4;
            asm volatile("cp.async.cg.shared.global [%0], [%1], 16;"
                         :: "r"(stg + idx * 16), "l"(src));
        }
        asm volatile("cp.async.commit_group;");

        // direct conversion of lo-d half (d 0..63)
#pragma unroll
        for (int q = 0; q < 8; q++) {
            int idx = q * 256 + t;
            int d = idx >> 5, p4 = idx & 31;
            float4 v = __ldg((const float4*)(xb + (size_t)d * 4096) + p4);
            float4 tf;
            tf.x = __uint_as_float(f2tf32(v.x));
            tf.y = __uint_as_float(f2tf32(v.y));
            tf.z = __uint_as_float(f2tf32(v.z));
            tf.w = __uint_as_float(f2tf32(v.w));
            *(float4*)(sb + d * 136 + p4 * 4) = tf;
        }
        __syncthreads();

        for (int half_ = 0; half_ < 2; half_++) {
            float acc[16][4];
#pragma unroll
            for (int j = 0; j < 16; j++)
#pragma unroll
                for (int c = 0; c < 4; c++) acc[j][c] = 0.f;

            const float4* pA = ((const float4*)g_A) +
                               (size_t)((m * 2 + half_) * 8 + wid) * 512;

            for (int kg = 0; kg < 2; kg++) {
                float4 afr[8];
#pragma unroll
                for (int ki = 0; ki < 8; ki++)
                    afr[ki] = __ldg(pA + (kg * 8 + ki) * 32 + lane);

                if (half_ == 0 && kg == 1) {
                    asm volatile("cp.async.wait_group 0;");
#pragma unroll
                    for (int q = 0; q < 8; q++) {
                        int idx = q * 256 + t;
                        int dh = idx >> 5, p4 = idx & 31;
                        float4 v = *(const float4*)(stage + idx * 4);
                        float4 tf;
                        tf.x = __uint_as_float(f2tf32(v.x));
                        tf.y = __uint_as_float(f2tf32(v.y));
                        tf.z = __uint_as_float(f2tf32(v.z));
                        tf.w = __uint_as_float(f2tf32(v.w));
                        *(float4*)(sb + (64 + dh) * 136 + p4 * 4) = tf;
                    }
                    __syncthreads();
                }
#pragma unroll
                for (int ki = 0; ki < 8; ki++) {
                    int ks = kg * 8 + ki;
                    const float* bbase = sb + (ks * 8 + (lane & 3)) * 136 + (lane >> 2);
#pragma unroll
                    for (int j = 0; j < 16; j++) {
                        float2 b = make_float2(bbase[j * 8], bbase[544 + j * 8]);
                        mma8(acc[j], afr[ki], b);
                    }
                }
            }

            // ---- top-2 over this warp's 16 codes, per pixel ----
            int r0 = half_ * 128 + wid * 16 + (lane >> 2);
#pragma unroll
            for (int j = 0; j < 16; j++) {
#pragma unroll
                for (int cc = 0; cc < 2; cc++) {
                    unsigned u0 = mono(acc[j][cc]);
                    unsigned u1 = mono(acc[j][2 + cc]);
                    ULL k0 = ((ULL)u0 << 32) | (unsigned)(255 - r0);
                    ULL k1 = ((ULL)u1 << 32) | (unsigned)(255 - (r0 + 8));
                    ULL key = (k0 > k1) ? k0 : k1;
                    unsigned us = (u0 < u1) ? u0 : u1;
#pragma unroll
                    for (int o = 4; o <= 16; o <<= 1) {
                        ULL ok = __shfl_xor_sync(0xffffffffu, key, o);
                        unsigned os = __shfl_xor_sync(0xffffffffu, us, o);
                        unsigned loser_b = (unsigned)(((key < ok) ? key : ok) >> 32);
                        unsigned win_s = (key > ok) ? us : os;
                        us = (loser_b > win_s) ? loser_b : win_s;
                        key = (key > ok) ? key : ok;
                    }
                    if (lane < 4) {
                        int px = j * 8 + lane * 2 + cc;
                        gkeys[(half_ * 8 + wid) * 128 + px] = key;
                        gsecs[(half_ * 8 + wid) * 128 + px] = us;
                    }
                }
            }
        }
        __syncthreads();

        if (t < 128) {
            int px = t;
            ULL k1 = gkeys[px];
            int g1 = 0;
            unsigned u2 = 0;
#pragma unroll
            for (int g = 1; g < 16; g++) {
                ULL kb = gkeys[g * 128 + px];
                if (kb > k1) {
                    unsigned pb = (unsigned)(k1 >> 32);
                    if (pb > u2) u2 = pb;
                    k1 = kb; g1 = g;
                } else {
                    unsigned pb = (unsigned)(kb >> 32);
                    if (pb > u2) u2 = pb;
                }
            }
            unsigned sw = gsecs[g1 * 128 + px];
            if (sw > u2) u2 = sw;
            float f1 = imono((unsigned)(k1 >> 32));
            float f2 = imono(u2);
            int code = 255 - (int)(k1 & 0xFF);
            int pix = n * 4096 + p0 + px;
            out[pix * 4 + m] = (float)code;
            if (f1 - f2 < GAP_TH) {
                int pos = atomicAdd(&g_cnt[m], 1);
                g_list[m * 65536 + pos] = pix;
            }
        }
        __syncthreads();   // protect gkeys/stage before next unit's cp.async
    }
}

// ---------------- stage 2: batched exact fp32 refine (flattened) ------------
__global__ __launch_bounds__(256, 2)
void refine_kernel(const float* __restrict__ latent, float* __restrict__ out) {
    __shared__ float xs[128 * 32];     // [d][e]
    __shared__ ULL redk[32 * 64];      // [e][c4]
    __shared__ int spix[32];

    const int t = threadIdx.x;
    const int c0 = g_cnt[0], c1 = g_cnt[1], c2 = g_cnt[2], c3 = g_cnt[3];
    const int nb0 = (c0 + 31) >> 5, nb1 = (c1 + 31) >> 5;
    const int nb2 = (c2 + 31) >> 5, nb3 = (c3 + 31) >> 5;
    const int tot = nb0 + nb1 + nb2 + nb3;

    for (int jb = blockIdx.x; jb < tot; jb += gridDim.x) {
        int m, lb, cnt;
        if (jb < nb0)                  { m = 0; lb = jb; cnt = c0; }
        else if (jb < nb0 + nb1)       { m = 1; lb = jb - nb0; cnt = c1; }
        else if (jb < nb0 + nb1 + nb2) { m = 2; lb = jb - nb0 - nb1; cnt = c2; }
        else                           { m = 3; lb = jb - nb0 - nb1 - nb2; cnt = c3; }
        int ne = cnt - lb * 32;
        if (ne > 32) ne = 32;

        if (t < 32)
            spix[t] = g_list[m * 65536 + lb * 32 + ((t < ne) ? t : 0)];
        __syncthreads();

        {
            int e = t & 31, d0 = (t >> 5) * 16;
            int pp = spix[e];
            const float* xp = latent +
                ((size_t)((pp >> 12) * 512 + m * 128 + d0)) * 4096 + (pp & 4095);
            float v[16];
#pragma unroll
            for (int i = 0; i < 16; i++) v[i] = __ldg(xp + (size_t)i * 4096);
#pragma unroll
            for (int i = 0; i < 16; i++) xs[(d0 + i) * 32 + e] = v[i];
        }
        __syncthreads();

        const int c4 = t & 63, eg = t >> 6;
        float acc[4][8];
#pragma unroll
        for (int c = 0; c < 4; c++)
#pragma unroll
            for (int k = 0; k < 8; k++) acc[c][k] = 0.f;

        const float4* MT = (const float4*)(g_MT + (size_t)m * 32768);
#pragma unroll 4
        for (int d = 0; d < 128; d++) {
            float4 mv = __ldg(MT + d * 64 + c4);
            float4 xa = *(const float4*)(xs + d * 32 + eg * 8);
            float4 xc = *(const float4*)(xs + d * 32 + eg * 8 + 4);
            float xv[8] = {xa.x, xa.y, xa.z, xa.w, xc.x, xc.y, xc.z, xc.w};
#pragma unroll
            for (int k = 0; k < 8; k++) {
                acc[0][k] += mv.x * xv[k];
                acc[1][k] += mv.y * xv[k];
                acc[2][k] += mv.z * xv[k];
                acc[3][k] += mv.w * xv[k];
            }
        }

#pragma unroll
        for (int k = 0; k < 8; k++) {
            ULL key = 0;
#pragma unroll
            for (int c = 0; c < 4; c++) {
                int code = c4 * 4 + c;
                ULL kk = ((ULL)mono(acc[c][k]) << 32) | (unsigned)(255 - code);
                if (kk > key) key = kk;
            }
            redk[(eg * 8 + k) * 64 + c4] = key;
        }
        __syncthreads();

        {
            int e2 = t >> 3, ch = t & 7;
            ULL best = redk[e2 * 64 + ch * 8];
#pragma unroll
            for (int q = 1; q < 8; q++) {
                ULL o = redk[e2 * 64 + ch * 8 + q];
                if (o > best) best = o;
            }
#pragma unroll
            for (int o = 1; o < 8; o <<= 1) {
                ULL ob = __shfl_xor_sync(0xffffffffu, best, o);
                if (ob > best) best = ob;
            }
            if (ch == 0 && e2 < ne)
                out[spix[e2] * 4 + m] = (float)(255 - (int)(best & 0xFF));
        }
        __syncthreads();
    }
}

extern "C" void kernel_launch(void* const* d_in, const int* in_sizes, int n_in,
                              void* d_out, int out_size) {
    const float* latent = (const float*)d_in[0];
    const float* cb     = (const float*)d_in[1];
    const float* wq     = (const float*)d_in[2];
    const float* wk     = (const float*)d_in[3];

    cudaFuncSetAttribute(setup_kernel, cudaFuncAttributeMaxDynamicSharedMemorySize, 74240);
    cudaFuncSetAttribute(score_kernel, cudaFuncAttributeMaxDynamicSharedMemorySize, 102400);

    setup_kernel<<<dim3(32, 4), 256, 74240>>>(cb, wk, wq);
    score_kernel<<<NCTA, 256, 102400>>>(latent, (float*)d_out);
    refine_kernel<<<512, 256>>>(latent, (float*)d_out);
}

// round 12
// speedup vs baseline: 1.2547x; 1.2547x over previous
#include <cuda_runtime.h>
#include <cstdint>

// ---------------------------------------------------------------------------
// QuantizerEncoder: 1-pass tf32 HMMA screen (wave-launched, 2 CTA/SM) with
// 32-bit-key argmax + ambiguity flags; flagged entries exactly recomputed
// in fp32 by refine_kernel.
//
//   score[code][px] = sum_d Mmat[code][d] * x[d][px]
//   out[n,h,w,m] = argmax_code score  (float-coded index)
// ---------------------------------------------------------------------------

typedef unsigned long long ULL;

__device__ float g_A[262144];             // tf32-hi, m16n8k8 A-frag layout
__device__ float g_MT[4 * 128 * 256];     // fp32 M^T [m][d][k] (refine)
__device__ int   g_cnt[4];                // flagged counts per m
__device__ int   g_list[4 * 65536];       // flagged pixel lists per m

#define GAP_TH 0.055f

static __device__ __forceinline__ uint32_t f2tf32(float v) {
    uint32_t u;
    asm("cvt.rna.tf32.f32 %0, %1;" : "=r"(u) : "f"(v));
    return u;
}

static __device__ __forceinline__ uint32_t smem_u32(const void* p) {
    uint32_t a;
    asm("{ .reg .u64 t; cvta.to.shared.u64 t, %1; cvt.u32.u64 %0, t; }"
        : "=r"(a) : "l"(p));
    return a;
}

static __device__ __forceinline__ void mma8(float* d, float4 a, float2 b) {
    asm volatile(
        "mma.sync.aligned.m16n8k8.row.col.f32.tf32.tf32.f32 "
        "{%0,%1,%2,%3}, {%4,%5,%6,%7}, {%8,%9}, {%0,%1,%2,%3};"
        : "+f"(d[0]), "+f"(d[1]), "+f"(d[2]), "+f"(d[3])
        : "r"(__float_as_uint(a.x)), "r"(__float_as_uint(a.y)),
          "r"(__float_as_uint(a.z)), "r"(__float_as_uint(a.w)),
          "r"(__float_as_uint(b.x)), "r"(__float_as_uint(b.y)));
}

static __device__ __forceinline__ unsigned mono(float f) {
    unsigned u = __float_as_uint(f);
    return (u & 0x80000000u) ? ~u : (u | 0x80000000u);
}
static __device__ __forceinline__ float imono(unsigned u) {
    return (u & 0x80000000u) ? __uint_as_float(u & 0x7fffffffu)
                             : __uint_as_float(~u);
}

// ---------------- fused setup: keys (smem) -> Mmat -> g_A/g_MT --------------
__global__ __launch_bounds__(256, 1)
void setup_kernel(const float* __restrict__ cb, const float* __restrict__ wk,
                  const float* __restrict__ wq) {
    extern __shared__ float sm[];
    float* skeys = sm + 16512;   // [8 k][128 c]
    float* scb   = sm + 17536;   // [8 k][128 d]
    const int m = blockIdx.y, kch = blockIdx.x, t = threadIdx.x;

    const float4* wk4 = (const float4*)(wk + (size_t)m * 16384);
#pragma unroll
    for (int i = 0; i < 16; i++) {
        int j = i * 256 + t, c = j >> 5, d4 = j & 31;
        float4 v = __ldg(wk4 + j);
        sm[(4 * d4 + 0) * 129 + c] = v.x;
        sm[(4 * d4 + 1) * 129 + c] = v.y;
        sm[(4 * d4 + 2) * 129 + c] = v.z;
        sm[(4 * d4 + 3) * 129 + c] = v.w;
    }
    ((float4*)scb)[t] = __ldg((const float4*)(cb + ((size_t)m * 256 + kch * 8) * 128) + t);
    __syncthreads();
    {
        int c = t & 127, b = t >> 7;
        float s0 = 0.f, s1 = 0.f, s2 = 0.f, s3 = 0.f;
#pragma unroll 8
        for (int d = 0; d < 128; d++) {
            float w = sm[d * 129 + c];
            s0 += scb[(b + 0) * 128 + d] * w;
            s1 += scb[(b + 2) * 128 + d] * w;
            s2 += scb[(b + 4) * 128 + d] * w;
            s3 += scb[(b + 6) * 128 + d] * w;
        }
        skeys[(b + 0) * 128 + c] = s0;
        skeys[(b + 2) * 128 + c] = s1;
        skeys[(b + 4) * 128 + c] = s2;
        skeys[(b + 6) * 128 + c] = s3;
    }
    __syncthreads();

    const float4* wq4 = (const float4*)(wq + (size_t)m * 16384);
#pragma unroll
    for (int i = 0; i < 16; i++) ((float4*)sm)[i * 256 + t] = __ldg(wq4 + i * 256 + t);
    __syncthreads();
    {
        int d = t & 127, b = t >> 7;
        float v0 = 0.f, v1 = 0.f, v2 = 0.f, v3 = 0.f;
#pragma unroll 8
        for (int c = 0; c < 128; c++) {
            float w = sm[c * 128 + d];
            v0 += w * skeys[(b + 0) * 128 + c];
            v1 += w * skeys[(b + 2) * 128 + c];
            v2 += w * skeys[(b + 4) * 128 + c];
            v3 += w * skeys[(b + 6) * 128 + c];
        }
        float vals[4] = {v0, v1, v2, v3};
#pragma unroll
        for (int q = 0; q < 4; q++) {
            int kl = b + 2 * q;
            int k = kch * 8 + kl;
            float val = vals[q];
            g_MT[((size_t)m * 128 + d) * 256 + k] = val;

            uint32_t hib = f2tf32(val);
            int half_ = k >> 7, w = (k & 127) >> 4, r = k & 15;
            int ks = d >> 3, dc = d & 7;
            int ln, fi;
            if (r < 8) { ln = r * 4 + (dc & 3); fi = (dc >= 4) ? 2 : 0; }
            else       { ln = (r - 8) * 4 + (dc & 3); fi = (dc >= 4) ? 3 : 1; }
            size_t base = (size_t)(((m * 2 + half_) * 8 + w) * 16 + ks) * 128 + ln * 4 + fi;
            g_A[base] = __uint_as_float(hib);
        }
    }
    if (blockIdx.x == 0 && blockIdx.y == 0 && t < 4) g_cnt[t] = 0;
}

// ---------------- stage 1: 1-pass tf32 + key32 argmax + flags ---------------
// CTA: 256 threads, 128 px, one m. grid = (512, 4). 2 CTAs/SM.
// smem floats: [0,17408) B tf32 [128 d][136]; stage @17408 (8192f raw hi-d);
// gk32 u32[16][128] @17408 and gflag u8[16][128] @19456 alias stage
// (stage dead before they are written). Total 102400 B.
__global__ __launch_bounds__(256, 2)
void score_kernel(const float* __restrict__ latent, float* __restrict__ out) {
    extern __shared__ float sb[];
    float* stage = sb + 17408;
    unsigned* gk32 = (unsigned*)(sb + 17408);
    unsigned char* gflag = (unsigned char*)(sb + 19456);

    const int t = threadIdx.x, lane = t & 31, wid = t >> 5;
    const int m = blockIdx.y;
    const int n = blockIdx.x >> 5;
    const int p0 = (blockIdx.x & 31) << 7;

    const float* xb = latent + ((size_t)(n * 512 + m * 128)) * 4096 + p0;
    const uint32_t stg = smem_u32(stage);

    // async stage of hi-d half (d 64..127) raw fp32
#pragma unroll
    for (int i = 0; i < 8; i++) {
        int idx = i * 256 + t;
        int dh = idx >> 5, p4 = idx & 31;
        const float* src = xb + (size_t)(64 + dh) * 4096 + p4 * 4;
        asm volatile("cp.async.cg.shared.global [%0], [%1], 16;"
                     :: "r"(stg + idx * 16), "l"(src));
    }
    asm volatile("cp.async.commit_group;");

    // direct conversion of lo-d half (d 0..63)
#pragma unroll
    for (int i = 0; i < 8; i++) {
        int idx = i * 256 + t;
        int d = idx >> 5, p4 = idx & 31;
        float4 v = __ldg((const float4*)(xb + (size_t)d * 4096) + p4);
        float4 tf;
        tf.x = __uint_as_float(f2tf32(v.x));
        tf.y = __uint_as_float(f2tf32(v.y));
        tf.z = __uint_as_float(f2tf32(v.z));
        tf.w = __uint_as_float(f2tf32(v.w));
        *(float4*)(sb + d * 136 + p4 * 4) = tf;
    }
    __syncthreads();

    for (int half_ = 0; half_ < 2; half_++) {
        float acc[16][4];
#pragma unroll
        for (int j = 0; j < 16; j++)
#pragma unroll
            for (int c = 0; c < 4; c++) acc[j][c] = 0.f;

        const float4* pA = ((const float4*)g_A) +
                           (size_t)((m * 2 + half_) * 8 + wid) * 512;

        for (int kg = 0; kg < 2; kg++) {
            float4 afr[8];
#pragma unroll
            for (int ki = 0; ki < 8; ki++)
                afr[ki] = __ldg(pA + (kg * 8 + ki) * 32 + lane);

            if (half_ == 0 && kg == 1) {
                asm volatile("cp.async.wait_group 0;");
#pragma unroll
                for (int i = 0; i < 8; i++) {
                    int idx = i * 256 + t;
                    int dh = idx >> 5, p4 = idx & 31;
                    float4 v = *(const float4*)(stage + idx * 4);
                    float4 tf;
                    tf.x = __uint_as_float(f2tf32(v.x));
                    tf.y = __uint_as_float(f2tf32(v.y));
                    tf.z = __uint_as_float(f2tf32(v.z));
                    tf.w = __uint_as_float(f2tf32(v.w));
                    *(float4*)(sb + (64 + dh) * 136 + p4 * 4) = tf;
                }
                __syncthreads();
            }
#pragma unroll
            for (int ki = 0; ki < 8; ki++) {
                int ks = kg * 8 + ki;
                const float* bbase = sb + (ks * 8 + (lane & 3)) * 136 + (lane >> 2);
#pragma unroll
                for (int j = 0; j < 16; j++) {
                    float2 b = make_float2(bbase[j * 8], bbase[544 + j * 8]);
                    mma8(acc[j], afr[ki], b);
                }
            }
        }

        // ---- key32 argmax + ambiguity flag over this warp's 16 codes ----
        int r0 = half_ * 128 + wid * 16 + (lane >> 2);
        const unsigned gm = 0x11111111u << (lane & 3);
#pragma unroll
        for (int j = 0; j < 16; j++) {
#pragma unroll
            for (int cc = 0; cc < 2; cc++) {
                float v0 = acc[j][cc];        // code r0
                float v1 = acc[j][2 + cc];    // code r0+8
                unsigned k0 = (mono(v0) & 0xFFFFFF00u) | (unsigned)(255 - r0);
                unsigned k1 = (mono(v1) & 0xFFFFFF00u) | (unsigned)(255 - (r0 + 8));
                unsigned key = (k0 > k1) ? k0 : k1;
#pragma unroll
                for (int o = 4; o <= 16; o <<= 1) {
                    unsigned ok = __shfl_xor_sync(0xffffffffu, key, o);
                    if (ok > key) key = ok;
                }
                int wincode = 255 - (int)(key & 0xFFu);
                float thr = imono(key & 0xFFFFFF00u) - GAP_TH;
                int excess = ((v0 >= thr) && (wincode != r0)) +
                             ((v1 >= thr) && (wincode != r0 + 8));
                unsigned bal = __ballot_sync(0xffffffffu, excess > 0);
                if (lane < 4) {
                    int px = j * 8 + lane * 2 + cc;
                    gk32[(half_ * 8 + wid) * 128 + px] = key;
                    gflag[(half_ * 8 + wid) * 128 + px] =
                        ((bal & gm) != 0u) ? 1 : 0;
                }
            }
        }
    }
    __syncthreads();

    if (t < 128) {
        int px = t;
        unsigned best = 0, sec = 0;
        int g1 = 0;
#pragma unroll
        for (int g = 0; g < 16; g++) {
            unsigned k = gk32[g * 128 + px];
            if (k > best) { sec = best; best = k; g1 = g; }
            else if (k > sec) sec = k;
        }
        float f1 = imono(best & 0xFFFFFF00u);
        float f2 = imono(sec & 0xFFFFFF00u);
        int code = 255 - (int)(best & 0xFFu);
        int pix = n * 4096 + p0 + px;
        out[pix * 4 + m] = (float)code;
        bool flag = (gflag[g1 * 128 + px] != 0) || (f1 - f2 < GAP_TH);
        if (flag) {
            int pos = atomicAdd(&g_cnt[m], 1);
            g_list[m * 65536 + pos] = pix;
        }
    }
}

// ---------------- stage 2: batched exact fp32 refine (flattened) ------------
__global__ __launch_bounds__(256, 2)
void refine_kernel(const float* __restrict__ latent, float* __restrict__ out) {
    __shared__ float xs[128 * 32];     // [d][e]
    __shared__ ULL redk[32 * 64];      // [e][c4]
    __shared__ int spix[32];

    const int t = threadIdx.x;
    const int c0 = g_cnt[0], c1 = g_cnt[1], c2 = g_cnt[2], c3 = g_cnt[3];
    const int nb0 = (c0 + 31) >> 5, nb1 = (c1 + 31) >> 5;
    const int nb2 = (c2 + 31) >> 5, nb3 = (c3 + 31) >> 5;
    const int tot = nb0 + nb1 + nb2 + nb3;

    for (int jb = blockIdx.x; jb < tot; jb += gridDim.x) {
        int m, lb, cnt;
        if (jb < nb0)                  { m = 0; lb = jb; cnt = c0; }
        else if (jb < nb0 + nb1)       { m = 1; lb = jb - nb0; cnt = c1; }
        else if (jb < nb0 + nb1 + nb2) { m = 2; lb = jb - nb0 - nb1; cnt = c2; }
        else                           { m = 3; lb = jb - nb0 - nb1 - nb2; cnt = c3; }
        int ne = cnt - lb * 32;
        if (ne > 32) ne = 32;

        if (t < 32)
            spix[t] = g_list[m * 65536 + lb * 32 + ((t < ne) ? t : 0)];
        __syncthreads();

        {
            int e = t & 31, d0 = (t >> 5) * 16;
            int pp = spix[e];
            const float* xp = latent +
                ((size_t)((pp >> 12) * 512 + m * 128 + d0)) * 4096 + (pp & 4095);
            float v[16];
#pragma unroll
            for (int i = 0; i < 16; i++) v[i] = __ldg(xp + (size_t)i * 4096);
#pragma unroll
            for (int i = 0; i < 16; i++) xs[(d0 + i) * 32 + e] = v[i];
        }
        __syncthreads();

        const int c4 = t & 63, eg = t >> 6;
        float acc[4][8];
#pragma unroll
        for (int c = 0; c < 4; c++)
#pragma unroll
            for (int k = 0; k < 8; k++) acc[c][k] = 0.f;

        const float4* MT = (const float4*)(g_MT + (size_t)m * 32768);
#pragma unroll 4
        for (int d = 0; d < 128; d++) {
            float4 mv = __ldg(MT + d * 64 + c4);
            float4 xa = *(const float4*)(xs + d * 32 + eg * 8);
            float4 xc = *(const float4*)(xs + d * 32 + eg * 8 + 4);
            float xv[8] = {xa.x, xa.y, xa.z, xa.w, xc.x, xc.y, xc.z, xc.w};
#pragma unroll
            for (int k = 0; k < 8; k++) {
                acc[0][k] += mv.x * xv[k];
                acc[1][k] += mv.y * xv[k];
                acc[2][k] += mv.z * xv[k];
                acc[3][k] += mv.w * xv[k];
            }
        }

#pragma unroll
        for (int k = 0; k < 8; k++) {
            ULL key = 0;
#pragma unroll
            for (int c = 0; c < 4; c++) {
                int code = c4 * 4 + c;
                ULL kk = ((ULL)mono(acc[c][k]) << 32) | (unsigned)(255 - code);
                if (kk > key) key = kk;
            }
            redk[(eg * 8 + k) * 64 + c4] = key;
        }
        __syncthreads();

        {
            int e2 = t >> 3, ch = t & 7;
            ULL best = redk[e2 * 64 + ch * 8];
#pragma unroll
            for (int q = 1; q < 8; q++) {
                ULL o = redk[e2 * 64 + ch * 8 + q];
                if (o > best) best = o;
            }
#pragma unroll
            for (int o = 1; o < 8; o <<= 1) {
                ULL ob = __shfl_xor_sync(0xffffffffu, best, o);
                if (ob > best) best = ob;
            }
            if (ch == 0 && e2 < ne)
                out[spix[e2] * 4 + m] = (float)(255 - (int)(best & 0xFF));
        }
        __syncthreads();
    }
}

extern "C" void kernel_launch(void* const* d_in, const int* in_sizes, int n_in,
                              void* d_out, int out_size) {
    const float* latent = (const float*)d_in[0];
    const float* cb     = (const float*)d_in[1];
    const float* wq     = (const float*)d_in[2];
    const float* wk     = (const float*)d_in[3];

    cudaFuncSetAttribute(setup_kernel, cudaFuncAttributeMaxDynamicSharedMemorySize, 74240);
    cudaFuncSetAttribute(score_kernel, cudaFuncAttributeMaxDynamicSharedMemorySize, 102400);

    setup_kernel<<<dim3(32, 4), 256, 74240>>>(cb, wk, wq);
    score_kernel<<<dim3(512, 4), 256, 102400>>>(latent, (float*)d_out);
    refine_kernel<<<512, 256>>>(latent, (float*)d_out);
}

// round 13
// speedup vs baseline: 1.3338x; 1.0631x over previous
#include <cuda_runtime.h>
#include <cstdint>

// ---------------------------------------------------------------------------
// QuantizerEncoder: 1-pass tf32 HMMA screen with raw-fp32 B operand
// (implicit tf32 truncation), cp.async-direct B tile, 32-bit-key argmax +
// ambiguity flags; flagged entries exactly recomputed in fp32.
//
//   score[code][px] = sum_d Mmat[code][d] * x[d][px]
//   out[n,h,w,m] = argmax_code score  (float-coded index)
// ---------------------------------------------------------------------------

typedef unsigned long long ULL;

__device__ float g_A[262144];             // tf32-hi (rounded), m16n8k8 A-frag layout
__device__ float g_MT[4 * 128 * 256];     // fp32 M^T [m][d][k] (refine)
__device__ int   g_cnt[4];                // flagged counts per m
__device__ int   g_list[4 * 65536];       // flagged pixel lists per m

// B-side is truncated (not rounded) tf32: pair-noise sigma ~= 0.010 -> 9 sigma
#define GAP_TH 0.09f

static __device__ __forceinline__ uint32_t f2tf32(float v) {
    uint32_t u;
    asm("cvt.rna.tf32.f32 %0, %1;" : "=r"(u) : "f"(v));
    return u;
}

static __device__ __forceinline__ uint32_t smem_u32(const void* p) {
    uint32_t a;
    asm("{ .reg .u64 t; cvta.to.shared.u64 t, %1; cvt.u32.u64 %0, t; }"
        : "=r"(a) : "l"(p));
    return a;
}

static __device__ __forceinline__ void mma8(float* d, float4 a, float2 b) {
    asm volatile(
        "mma.sync.aligned.m16n8k8.row.col.f32.tf32.tf32.f32 "
        "{%0,%1,%2,%3}, {%4,%5,%6,%7}, {%8,%9}, {%0,%1,%2,%3};"
        : "+f"(d[0]), "+f"(d[1]), "+f"(d[2]), "+f"(d[3])
        : "r"(__float_as_uint(a.x)), "r"(__float_as_uint(a.y)),
          "r"(__float_as_uint(a.z)), "r"(__float_as_uint(a.w)),
          "r"(__float_as_uint(b.x)), "r"(__float_as_uint(b.y)));
}

static __device__ __forceinline__ unsigned mono(float f) {
    unsigned u = __float_as_uint(f);
    return (u & 0x80000000u) ? ~u : (u | 0x80000000u);
}
static __device__ __forceinline__ float imono(unsigned u) {
    return (u & 0x80000000u) ? __uint_as_float(u & 0x7fffffffu)
                             : __uint_as_float(~u);
}

// ---------------- fused setup: keys (smem) -> Mmat -> g_A/g_MT --------------
__global__ __launch_bounds__(256, 1)
void setup_kernel(const float* __restrict__ cb, const float* __restrict__ wk,
                  const float* __restrict__ wq) {
    extern __shared__ float sm[];
    float* skeys = sm + 16512;   // [8 k][128 c]
    float* scb   = sm + 17536;   // [8 k][128 d]
    const int m = blockIdx.y, kch = blockIdx.x, t = threadIdx.x;

    const float4* wk4 = (const float4*)(wk + (size_t)m * 16384);
#pragma unroll
    for (int i = 0; i < 16; i++) {
        int j = i * 256 + t, c = j >> 5, d4 = j & 31;
        float4 v = __ldg(wk4 + j);
        sm[(4 * d4 + 0) * 129 + c] = v.x;
        sm[(4 * d4 + 1) * 129 + c] = v.y;
        sm[(4 * d4 + 2) * 129 + c] = v.z;
        sm[(4 * d4 + 3) * 129 + c] = v.w;
    }
    ((float4*)scb)[t] = __ldg((const float4*)(cb + ((size_t)m * 256 + kch * 8) * 128) + t);
    __syncthreads();
    {
        int c = t & 127, b = t >> 7;
        float s0 = 0.f, s1 = 0.f, s2 = 0.f, s3 = 0.f;
#pragma unroll 8
        for (int d = 0; d < 128; d++) {
            float w = sm[d * 129 + c];
            s0 += scb[(b + 0) * 128 + d] * w;
            s1 += scb[(b + 2) * 128 + d] * w;
            s2 += scb[(b + 4) * 128 + d] * w;
            s3 += scb[(b + 6) * 128 + d] * w;
        }
        skeys[(b + 0) * 128 + c] = s0;
        skeys[(b + 2) * 128 + c] = s1;
        skeys[(b + 4) * 128 + c] = s2;
        skeys[(b + 6) * 128 + c] = s3;
    }
    __syncthreads();

    const float4* wq4 = (const float4*)(wq + (size_t)m * 16384);
#pragma unroll
    for (int i = 0; i < 16; i++) ((float4*)sm)[i * 256 + t] = __ldg(wq4 + i * 256 + t);
    __syncthreads();
    {
        int d = t & 127, b = t >> 7;
        float v0 = 0.f, v1 = 0.f, v2 = 0.f, v3 = 0.f;
#pragma unroll 8
        for (int c = 0; c < 128; c++) {
            float w = sm[c * 128 + d];
            v0 += w * skeys[(b + 0) * 128 + c];
            v1 += w * skeys[(b + 2) * 128 + c];
            v2 += w * skeys[(b + 4) * 128 + c];
            v3 += w * skeys[(b + 6) * 128 + c];
        }
        float vals[4] = {v0, v1, v2, v3};
#pragma unroll
        for (int q = 0; q < 4; q++) {
            int kl = b + 2 * q;
            int k = kch * 8 + kl;
            float val = vals[q];
            g_MT[((size_t)m * 128 + d) * 256 + k] = val;

            uint32_t hib = f2tf32(val);
            int half_ = k >> 7, w = (k & 127) >> 4, r = k & 15;
            int ks = d >> 3, dc = d & 7;
            int ln, fi;
            if (r < 8) { ln = r * 4 + (dc & 3); fi = (dc >= 4) ? 2 : 0; }
            else       { ln = (r - 8) * 4 + (dc & 3); fi = (dc >= 4) ? 3 : 1; }
            size_t base = (size_t)(((m * 2 + half_) * 8 + w) * 16 + ks) * 128 + ln * 4 + fi;
            g_A[base] = __uint_as_float(hib);
        }
    }
    if (blockIdx.x == 0 && blockIdx.y == 0 && t < 4) g_cnt[t] = 0;
}

// ---------------- stage 1: raw-B tf32 screen + key32 argmax + flags ---------
// CTA: 256 threads, 128 px, one m. grid = (512, 4). 2 CTAs/SM.
// smem floats: [0,17408) B raw fp32 [128 d][136] (cp.async direct);
// gk32 u32[16][128] @17408 (8KB); gflag u8[16][128] @19456 (2KB). 79872 B.
__global__ __launch_bounds__(256, 2)
void score_kernel(const float* __restrict__ latent, float* __restrict__ out) {
    extern __shared__ float sb[];
    unsigned* gk32 = (unsigned*)(sb + 17408);
    unsigned char* gflag = (unsigned char*)(sb + 19456);

    const int t = threadIdx.x, lane = t & 31, wid = t >> 5;
    const int m = blockIdx.y;
    const int n = blockIdx.x >> 5;
    const int p0 = (blockIdx.x & 31) << 7;

    const float* xb = latent + ((size_t)(n * 512 + m * 128)) * 4096 + p0;
    const uint32_t bB = smem_u32(sb);

    // cp.async both halves straight into B[d][136] (raw fp32 == tf32-truncated
    // when consumed by HMMA). Group order: lo-d committed first.
#pragma unroll
    for (int i = 0; i < 8; i++) {
        int idx = i * 256 + t;             // d 0..63
        int d = idx >> 5, p4 = idx & 31;
        const float* src = xb + (size_t)d * 4096 + p4 * 4;
        asm volatile("cp.async.cg.shared.global [%0], [%1], 16;"
                     :: "r"(bB + (d * 136 + p4 * 4) * 4), "l"(src));
    }
    asm volatile("cp.async.commit_group;");
#pragma unroll
    for (int i = 8; i < 16; i++) {
        int idx = i * 256 + t;             // d 64..127
        int d = idx >> 5, p4 = idx & 31;
        const float* src = xb + (size_t)d * 4096 + p4 * 4;
        asm volatile("cp.async.cg.shared.global [%0], [%1], 16;"
                     :: "r"(bB + (d * 136 + p4 * 4) * 4), "l"(src));
    }
    asm volatile("cp.async.commit_group;");

    bool lo_ready = false, hi_ready = false;

    for (int half_ = 0; half_ < 2; half_++) {
        float acc[16][4];
#pragma unroll
        for (int j = 0; j < 16; j++)
#pragma unroll
            for (int c = 0; c < 4; c++) acc[j][c] = 0.f;

        const float4* pA = ((const float4*)g_A) +
                           (size_t)((m * 2 + half_) * 8 + wid) * 512;

        for (int kg = 0; kg < 2; kg++) {
            float4 afr[8];
#pragma unroll
            for (int ki = 0; ki < 8; ki++)
                afr[ki] = __ldg(pA + (kg * 8 + ki) * 32 + lane);

            if (kg == 0 && !lo_ready) {
                asm volatile("cp.async.wait_group 1;");
                __syncthreads();
                lo_ready = true;
            } else if (kg == 1 && !hi_ready) {
                asm volatile("cp.async.wait_group 0;");
                __syncthreads();
                hi_ready = true;
            }
#pragma unroll
            for (int ki = 0; ki < 8; ki++) {
                int ks = kg * 8 + ki;
                const float* bbase = sb + (ks * 8 + (lane & 3)) * 136 + (lane >> 2);
#pragma unroll
                for (int j = 0; j < 16; j++) {
                    float2 b = make_float2(bbase[j * 8], bbase[544 + j * 8]);
                    mma8(acc[j], afr[ki], b);
                }
            }
        }

        // ---- key32 argmax + ambiguity flag over this warp's 16 codes ----
        int r0 = half_ * 128 + wid * 16 + (lane >> 2);
        const unsigned gm = 0x11111111u << (lane & 3);
#pragma unroll
        for (int j = 0; j < 16; j++) {
#pragma unroll
            for (int cc = 0; cc < 2; cc++) {
                float v0 = acc[j][cc];        // code r0
                float v1 = acc[j][2 + cc];    // code r0+8
                unsigned k0 = (mono(v0) & 0xFFFFFF00u) | (unsigned)(255 - r0);
                unsigned k1 = (mono(v1) & 0xFFFFFF00u) | (unsigned)(255 - (r0 + 8));
                unsigned key = (k0 > k1) ? k0 : k1;
#pragma unroll
                for (int o = 4; o <= 16; o <<= 1) {
                    unsigned ok = __shfl_xor_sync(0xffffffffu, key, o);
                    if (ok > key) key = ok;
                }
                int wincode = 255 - (int)(key & 0xFFu);
                float thr = imono(key & 0xFFFFFF00u) - GAP_TH;
                int excess = ((v0 >= thr) && (wincode != r0)) +
                             ((v1 >= thr) && (wincode != r0 + 8));
                unsigned bal = __ballot_sync(0xffffffffu, excess > 0);
                if (lane < 4) {
                    int px = j * 8 + lane * 2 + cc;
                    gk32[(half_ * 8 + wid) * 128 + px] = key;
                    gflag[(half_ * 8 + wid) * 128 + px] =
                        ((bal & gm) != 0u) ? 1 : 0;
                }
            }
        }
    }
    __syncthreads();

    if (t < 128) {
        int px = t;
        unsigned best = 0, sec = 0;
        int g1 = 0;
#pragma unroll
        for (int g = 0; g < 16; g++) {
            unsigned k = gk32[g * 128 + px];
            if (k > best) { sec = best; best = k; g1 = g; }
            else if (k > sec) sec = k;
        }
        float f1 = imono(best & 0xFFFFFF00u);
        float f2 = imono(sec & 0xFFFFFF00u);
        int code = 255 - (int)(best & 0xFFu);
        int pix = n * 4096 + p0 + px;
        out[pix * 4 + m] = (float)code;
        bool flag = (gflag[g1 * 128 + px] != 0) || (f1 - f2 < GAP_TH);
        if (flag) {
            int pos = atomicAdd(&g_cnt[m], 1);
            g_list[m * 65536 + pos] = pix;
        }
    }
}

// ---------------- stage 2: batched exact fp32 refine (flattened) ------------
__global__ __launch_bounds__(256, 2)
void refine_kernel(const float* __restrict__ latent, float* __restrict__ out) {
    __shared__ float xs[128 * 32];     // [d][e]
    __shared__ ULL redk[32 * 64];      // [e][c4]
    __shared__ int spix[32];

    const int t = threadIdx.x;
    const int c0 = g_cnt[0], c1 = g_cnt[1], c2 = g_cnt[2], c3 = g_cnt[3];
    const int nb0 = (c0 + 31) >> 5, nb1 = (c1 + 31) >> 5;
    const int nb2 = (c2 + 31) >> 5, nb3 = (c3 + 31) >> 5;
    const int tot = nb0 + nb1 + nb2 + nb3;

    for (int jb = blockIdx.x; jb < tot; jb += gridDim.x) {
        int m, lb, cnt;
        if (jb < nb0)                  { m = 0; lb = jb; cnt = c0; }
        else if (jb < nb0 + nb1)       { m = 1; lb = jb - nb0; cnt = c1; }
        else if (jb < nb0 + nb1 + nb2) { m = 2; lb = jb - nb0 - nb1; cnt = c2; }
        else                           { m = 3; lb = jb - nb0 - nb1 - nb2; cnt = c3; }
        int ne = cnt - lb * 32;
        if (ne > 32) ne = 32;

        if (t < 32)
            spix[t] = g_list[m * 65536 + lb * 32 + ((t < ne) ? t : 0)];
        __syncthreads();

        {
            int e = t & 31, d0 = (t >> 5) * 16;
            int pp = spix[e];
            const float* xp = latent +
                ((size_t)((pp >> 12) * 512 + m * 128 + d0)) * 4096 + (pp & 4095);
            float v[16];
#pragma unroll
            for (int i = 0; i < 16; i++) v[i] = __ldg(xp + (size_t)i * 4096);
#pragma unroll
            for (int i = 0; i < 16; i++) xs[(d0 + i) * 32 + e] = v[i];
        }
        __syncthreads();

        const int c4 = t & 63, eg = t >> 6;
        float acc[4][8];
#pragma unroll
        for (int c = 0; c < 4; c++)
#pragma unroll
            for (int k = 0; k < 8; k++) acc[c][k] = 0.f;

        const float4* MT = (const float4*)(g_MT + (size_t)m * 32768);
#pragma unroll 4
        for (int d = 0; d < 128; d++) {
            float4 mv = __ldg(MT + d * 64 + c4);
            float4 xa = *(const float4*)(xs + d * 32 + eg * 8);
            float4 xc = *(const float4*)(xs + d * 32 + eg * 8 + 4);
            float xv[8] = {xa.x, xa.y, xa.z, xa.w, xc.x, xc.y, xc.z, xc.w};
#pragma unroll
            for (int k = 0; k < 8; k++) {
                acc[0][k] += mv.x * xv[k];
                acc[1][k] += mv.y * xv[k];
                acc[2][k] += mv.z * xv[k];
                acc[3][k] += mv.w * xv[k];
            }
        }

#pragma unroll
        for (int k = 0; k < 8; k++) {
            ULL key = 0;
#pragma unroll
            for (int c = 0; c < 4; c++) {
                int code = c4 * 4 + c;
                ULL kk = ((ULL)mono(acc[c][k]) << 32) | (unsigned)(255 - code);
                if (kk > key) key = kk;
            }
            redk[(eg * 8 + k) * 64 + c4] = key;
        }
        __syncthreads();

        {
            int e2 = t >> 3, ch = t & 7;
            ULL best = redk[e2 * 64 + ch * 8];
#pragma unroll
            for (int q = 1; q < 8; q++) {
                ULL o = redk[e2 * 64 + ch * 8 + q];
                if (o > best) best = o;
            }
#pragma unroll
            for (int o = 1; o < 8; o <<= 1) {
                ULL ob = __shfl_xor_sync(0xffffffffu, best, o);
                if (ob > best) best = ob;
            }
            if (ch == 0 && e2 < ne)
                out[spix[e2] * 4 + m] = (float)(255 - (int)(best & 0xFF));
        }
        __syncthreads();
    }
}

extern "C" void kernel_launch(void* const* d_in, const int* in_sizes, int n_in,
                              void* d_out, int out_size) {
    const float* latent = (const float*)d_in[0];
    const float* cb     = (const float*)d_in[1];
    const float* wq     = (const float*)d_in[2];
    const float* wk     = (const float*)d_in[3];

    cudaFuncSetAttribute(setup_kernel, cudaFuncAttributeMaxDynamicSharedMemorySize, 74240);
    cudaFuncSetAttribute(score_kernel, cudaFuncAttributeMaxDynamicSharedMemorySize, 79872);

    setup_kernel<<<dim3(32, 4), 256, 74240>>>(cb, wk, wq);
    score_kernel<<<dim3(512, 4), 256, 79872>>>(latent, (float*)d_out);
    refine_kernel<<<512, 256>>>(latent, (float*)d_out);
}

// round 14
// speedup vs baseline: 1.3504x; 1.0125x over previous
#include <cuda_runtime.h>
#include <cstdint>

// ---------------------------------------------------------------------------
// QuantizerEncoder: 1-pass tf32 HMMA screen with raw-fp32 B operand
// (implicit tf32 truncation), cp.async-direct B tile, 32-bit-key argmax +
// ambiguity flags; flagged entries exactly recomputed in fp32.
//
//   score[code][px] = sum_d Mmat[code][d] * x[d][px]
//   out[n,h,w,m] = argmax_code score  (float-coded index)
// ---------------------------------------------------------------------------

typedef unsigned long long ULL;

__device__ float g_A[262144];             // tf32-hi (rounded), m16n8k8 A-frag layout
__device__ float g_MT[4 * 128 * 256];     // fp32 M^T [m][d][k] (refine)
__device__ int   g_cnt[4];                // flagged counts per m
__device__ int   g_list[4 * 65536];       // flagged pixel lists per m

// B-side is truncated (not rounded) tf32: pair-noise sigma ~= 0.010 -> 9 sigma
#define GAP_TH 0.09f

static __device__ __forceinline__ uint32_t f2tf32(float v) {
    uint32_t u;
    asm("cvt.rna.tf32.f32 %0, %1;" : "=r"(u) : "f"(v));
    return u;
}

static __device__ __forceinline__ uint32_t smem_u32(const void* p) {
    uint32_t a;
    asm("{ .reg .u64 t; cvta.to.shared.u64 t, %1; cvt.u32.u64 %0, t; }"
        : "=r"(a) : "l"(p));
    return a;
}

static __device__ __forceinline__ void mma8(float* d, float4 a, float2 b) {
    asm volatile(
        "mma.sync.aligned.m16n8k8.row.col.f32.tf32.tf32.f32 "
        "{%0,%1,%2,%3}, {%4,%5,%6,%7}, {%8,%9}, {%0,%1,%2,%3};"
        : "+f"(d[0]), "+f"(d[1]), "+f"(d[2]), "+f"(d[3])
        : "r"(__float_as_uint(a.x)), "r"(__float_as_uint(a.y)),
          "r"(__float_as_uint(a.z)), "r"(__float_as_uint(a.w)),
          "r"(__float_as_uint(b.x)), "r"(__float_as_uint(b.y)));
}

static __device__ __forceinline__ unsigned mono(float f) {
    unsigned u = __float_as_uint(f);
    return (u & 0x80000000u) ? ~u : (u | 0x80000000u);
}
static __device__ __forceinline__ float imono(unsigned u) {
    return (u & 0x80000000u) ? __uint_as_float(u & 0x7fffffffu)
                             : __uint_as_float(~u);
}

// ---------------- fused setup: keys (smem) -> Mmat -> g_A/g_MT --------------
// grid (64, 4), 256 threads, 4 k-codes per block, 2 blocks/SM.
// smem: swkT/swq region [0,16512), skeys @16512 (512 f), scb @17024 (512 f).
// Total 17536 f = 70144 B -> 2 blocks/SM (140 KB).
__global__ __launch_bounds__(256, 2)
void setup_kernel(const float* __restrict__ cb, const float* __restrict__ wk,
                  const float* __restrict__ wq) {
    extern __shared__ float sm[];
    float* skeys = sm + 16512;   // [4 k][128 c]
    float* scb   = sm + 17024;   // [4 k][128 d]
    const int m = blockIdx.y, kch = blockIdx.x, t = threadIdx.x;

    // phase 1: keys[k][c] = sum_d cb[k][d] * wk[c][d]   (k = kch*4 .. +3)
    const float4* wk4 = (const float4*)(wk + (size_t)m * 16384);
#pragma unroll
    for (int i = 0; i < 16; i++) {
        int j = i * 256 + t, c = j >> 5, d4 = j & 31;
        float4 v = __ldg(wk4 + j);
        sm[(4 * d4 + 0) * 129 + c] = v.x;
        sm[(4 * d4 + 1) * 129 + c] = v.y;
        sm[(4 * d4 + 2) * 129 + c] = v.z;
        sm[(4 * d4 + 3) * 129 + c] = v.w;
    }
    if (t < 128)
        ((float4*)scb)[t] =
            __ldg((const float4*)(cb + ((size_t)m * 256 + kch * 4) * 128) + t);
    __syncthreads();
    {
        int c = t & 127, b = t >> 7;       // b in {0,1}; k-locals b, b+2
        float s0 = 0.f, s1 = 0.f;
#pragma unroll 8
        for (int d = 0; d < 128; d++) {
            float w = sm[d * 129 + c];
            s0 += scb[(b + 0) * 128 + d] * w;   // warp-uniform scb -> broadcast
            s1 += scb[(b + 2) * 128 + d] * w;
        }
        skeys[(b + 0) * 128 + c] = s0;
        skeys[(b + 2) * 128 + c] = s1;
    }
    __syncthreads();

    // phase 2: Mmat[k][d] = sum_c wq[c][d] * keys[k][c]
    const float4* wq4 = (const float4*)(wq + (size_t)m * 16384);
#pragma unroll
    for (int i = 0; i < 16; i++) ((float4*)sm)[i * 256 + t] = __ldg(wq4 + i * 256 + t);
    __syncthreads();
    {
        int d = t & 127, b = t >> 7;
        float v0 = 0.f, v1 = 0.f;
#pragma unroll 8
        for (int c = 0; c < 128; c++) {
            float w = sm[c * 128 + d];
            v0 += w * skeys[(b + 0) * 128 + c];
            v1 += w * skeys[(b + 2) * 128 + c];
        }
        float vals[2] = {v0, v1};
#pragma unroll
        for (int q = 0; q < 2; q++) {
            int kl = b + 2 * q;
            int k = kch * 4 + kl;
            float val = vals[q];
            g_MT[((size_t)m * 128 + d) * 256 + k] = val;

            uint32_t hib = f2tf32(val);
            int half_ = k >> 7, w = (k & 127) >> 4, r = k & 15;
            int ks = d >> 3, dc = d & 7;
            int ln, fi;
            if (r < 8) { ln = r * 4 + (dc & 3); fi = (dc >= 4) ? 2 : 0; }
            else       { ln = (r - 8) * 4 + (dc & 3); fi = (dc >= 4) ? 3 : 1; }
            size_t base = (size_t)(((m * 2 + half_) * 8 + w) * 16 + ks) * 128 + ln * 4 + fi;
            g_A[base] = __uint_as_float(hib);
        }
    }
    if (blockIdx.x == 0 && blockIdx.y == 0 && t < 4) g_cnt[t] = 0;
}

// ---------------- stage 1: raw-B tf32 screen + key32 argmax + flags ---------
// CTA: 256 threads, 128 px, one m. grid = (512, 4). 2 CTAs/SM.
// smem floats: [0,17408) B raw fp32 [128 d][136] (cp.async direct);
// gk32 u32[16][128] @17408 (8KB); gflag u8[16][128] @19456 (2KB). 79872 B.
__global__ __launch_bounds__(256, 2)
void score_kernel(const float* __restrict__ latent, float* __restrict__ out) {
    extern __shared__ float sb[];
    unsigned* gk32 = (unsigned*)(sb + 17408);
    unsigned char* gflag = (unsigned char*)(sb + 19456);

    const int t = threadIdx.x, lane = t & 31, wid = t >> 5;
    const int m = blockIdx.y;
    const int n = blockIdx.x >> 5;
    const int p0 = (blockIdx.x & 31) << 7;

    const float* xb = latent + ((size_t)(n * 512 + m * 128)) * 4096 + p0;
    const uint32_t bB = smem_u32(sb);

    // cp.async both halves straight into B[d][136] (raw fp32 == tf32-truncated
    // when consumed by HMMA). Group order: lo-d committed first.
#pragma unroll
    for (int i = 0; i < 8; i++) {
        int idx = i * 256 + t;             // d 0..63
        int d = idx >> 5, p4 = idx & 31;
        const float* src = xb + (size_t)d * 4096 + p4 * 4;
        asm volatile("cp.async.cg.shared.global [%0], [%1], 16;"
                     :: "r"(bB + (d * 136 + p4 * 4) * 4), "l"(src));
    }
    asm volatile("cp.async.commit_group;");
#pragma unroll
    for (int i = 8; i < 16; i++) {
        int idx = i * 256 + t;             // d 64..127
        int d = idx >> 5, p4 = idx & 31;
        const float* src = xb + (size_t)d * 4096 + p4 * 4;
        asm volatile("cp.async.cg.shared.global [%0], [%1], 16;"
                     :: "r"(bB + (d * 136 + p4 * 4) * 4), "l"(src));
    }
    asm volatile("cp.async.commit_group;");

    bool lo_ready = false, hi_ready = false;

    for (int half_ = 0; half_ < 2; half_++) {
        float acc[16][4];
#pragma unroll
        for (int j = 0; j < 16; j++)
#pragma unroll
            for (int c = 0; c < 4; c++) acc[j][c] = 0.f;

        const float4* pA = ((const float4*)g_A) +
                           (size_t)((m * 2 + half_) * 8 + wid) * 512;

        for (int kg = 0; kg < 2; kg++) {
            float4 afr[8];
#pragma unroll
            for (int ki = 0; ki < 8; ki++)
                afr[ki] = __ldg(pA + (kg * 8 + ki) * 32 + lane);

            if (kg == 0 && !lo_ready) {
                asm volatile("cp.async.wait_group 1;");
                __syncthreads();
                lo_ready = true;
            } else if (kg == 1 && !hi_ready) {
                asm volatile("cp.async.wait_group 0;");
                __syncthreads();
                hi_ready = true;
            }
#pragma unroll
            for (int ki = 0; ki < 8; ki++) {
                int ks = kg * 8 + ki;
                const float* bbase = sb + (ks * 8 + (lane & 3)) * 136 + (lane >> 2);
#pragma unroll
                for (int j = 0; j < 16; j++) {
                    float2 b = make_float2(bbase[j * 8], bbase[544 + j * 8]);
                    mma8(acc[j], afr[ki], b);
                }
            }
        }

        // ---- key32 argmax + ambiguity flag over this warp's 16 codes ----
        int r0 = half_ * 128 + wid * 16 + (lane >> 2);
        const unsigned gm = 0x11111111u << (lane & 3);
#pragma unroll
        for (int j = 0; j < 16; j++) {
#pragma unroll
            for (int cc = 0; cc < 2; cc++) {
                float v0 = acc[j][cc];        // code r0
                float v1 = acc[j][2 + cc];    // code r0+8
                unsigned k0 = (mono(v0) & 0xFFFFFF00u) | (unsigned)(255 - r0);
                unsigned k1 = (mono(v1) & 0xFFFFFF00u) | (unsigned)(255 - (r0 + 8));
                unsigned key = (k0 > k1) ? k0 : k1;
#pragma unroll
                for (int o = 4; o <= 16; o <<= 1) {
                    unsigned ok = __shfl_xor_sync(0xffffffffu, key, o);
                    if (ok > key) key = ok;
                }
                int wincode = 255 - (int)(key & 0xFFu);
                float thr = imono(key & 0xFFFFFF00u) - GAP_TH;
                int excess = ((v0 >= thr) && (wincode != r0)) +
                             ((v1 >= thr) && (wincode != r0 + 8));
                unsigned bal = __ballot_sync(0xffffffffu, excess > 0);
                if (lane < 4) {
                    int px = j * 8 + lane * 2 + cc;
                    gk32[(half_ * 8 + wid) * 128 + px] = key;
                    gflag[(half_ * 8 + wid) * 128 + px] =
                        ((bal & gm) != 0u) ? 1 : 0;
                }
            }
        }
    }
    __syncthreads();

    if (t < 128) {
        int px = t;
        unsigned best = 0, sec = 0;
        int g1 = 0;
#pragma unroll
        for (int g = 0; g < 16; g++) {
            unsigned k = gk32[g * 128 + px];
            if (k > best) { sec = best; best = k; g1 = g; }
            else if (k > sec) sec = k;
        }
        float f1 = imono(best & 0xFFFFFF00u);
        float f2 = imono(sec & 0xFFFFFF00u);
        int code = 255 - (int)(best & 0xFFu);
        int pix = n * 4096 + p0 + px;
        out[pix * 4 + m] = (float)code;
        bool flag = (gflag[g1 * 128 + px] != 0) || (f1 - f2 < GAP_TH);
        if (flag) {
            int pos = atomicAdd(&g_cnt[m], 1);
            g_list[m * 65536 + pos] = pix;
        }
    }
}

// ---------------- stage 2: batched exact fp32 refine (flattened) ------------
__global__ __launch_bounds__(256, 2)
void refine_kernel(const float* __restrict__ latent, float* __restrict__ out) {
    __shared__ float xs[128 * 32];     // [d][e]
    __shared__ ULL redk[32 * 64];      // [e][c4]
    __shared__ int spix[32];

    const int t = threadIdx.x;
    const int c0 = g_cnt[0], c1 = g_cnt[1], c2 = g_cnt[2], c3 = g_cnt[3];
    const int nb0 = (c0 + 31) >> 5, nb1 = (c1 + 31) >> 5;
    const int nb2 = (c2 + 31) >> 5, nb3 = (c3 + 31) >> 5;
    const int tot = nb0 + nb1 + nb2 + nb3;

    for (int jb = blockIdx.x; jb < tot; jb += gridDim.x) {
        int m, lb, cnt;
        if (jb < nb0)                  { m = 0; lb = jb; cnt = c0; }
        else if (jb < nb0 + nb1)       { m = 1; lb = jb - nb0; cnt = c1; }
        else if (jb < nb0 + nb1 + nb2) { m = 2; lb = jb - nb0 - nb1; cnt = c2; }
        else                           { m = 3; lb = jb - nb0 - nb1 - nb2; cnt = c3; }
        int ne = cnt - lb * 32;
        if (ne > 32) ne = 32;

        if (t < 32)
            spix[t] = g_list[m * 65536 + lb * 32 + ((t < ne) ? t : 0)];
        __syncthreads();

        {
            int e = t & 31, d0 = (t >> 5) * 16;
            int pp = spix[e];
            const float* xp = latent +
                ((size_t)((pp >> 12) * 512 + m * 128 + d0)) * 4096 + (pp & 4095);
            float v[16];
#pragma unroll
            for (int i = 0; i < 16; i++) v[i] = __ldg(xp + (size_t)i * 4096);
#pragma unroll
            for (int i = 0; i < 16; i++) xs[(d0 + i) * 32 + e] = v[i];
        }
        __syncthreads();

        const int c4 = t & 63, eg = t >> 6;
        float acc[4][8];
#pragma unroll
        for (int c = 0; c < 4; c++)
#pragma unroll
            for (int k = 0; k < 8; k++) acc[c][k] = 0.f;

        const float4* MT = (const float4*)(g_MT + (size_t)m * 32768);
#pragma unroll 8
        for (int d = 0; d < 128; d++) {
            float4 mv = __ldg(MT + d * 64 + c4);
            float4 xa = *(const float4*)(xs + d * 32 + eg * 8);
            float4 xc = *(const float4*)(xs + d * 32 + eg * 8 + 4);
            float xv[8] = {xa.x, xa.y, xa.z, xa.w, xc.x, xc.y, xc.z, xc.w};
#pragma unroll
            for (int k = 0; k < 8; k++) {
                acc[0][k] += mv.x * xv[k];
                acc[1][k] += mv.y * xv[k];
                acc[2][k] += mv.z * xv[k];
                acc[3][k] += mv.w * xv[k];
            }
        }

#pragma unroll
        for (int k = 0; k < 8; k++) {
            ULL key = 0;
#pragma unroll
            for (int c = 0; c < 4; c++) {
                int code = c4 * 4 + c;
                ULL kk = ((ULL)mono(acc[c][k]) << 32) | (unsigned)(255 - code);
                if (kk > key) key = kk;
            }
            redk[(eg * 8 + k) * 64 + c4] = key;
        }
        __syncthreads();

        {
            int e2 = t >> 3, ch = t & 7;
            ULL best = redk[e2 * 64 + ch * 8];
#pragma unroll
            for (int q = 1; q < 8; q++) {
                ULL o = redk[e2 * 64 + ch * 8 + q];
                if (o > best) best = o;
            }
#pragma unroll
            for (int o = 1; o < 8; o <<= 1) {
                ULL ob = __shfl_xor_sync(0xffffffffu, best, o);
                if (ob > best) best = ob;
            }
            if (ch == 0 && e2 < ne)
                out[spix[e2] * 4 + m] = (float)(255 - (int)(best & 0xFF));
        }
        __syncthreads();
    }
}

extern "C" void kernel_launch(void* const* d_in, const int* in_sizes, int n_in,
                              void* d_out, int out_size) {
    const float* latent = (const float*)d_in[0];
    const float* cb     = (const float*)d_in[1];
    const float* wq     = (const float*)d_in[2];
    const float* wk     = (const float*)d_in[3];

    cudaFuncSetAttribute(setup_kernel, cudaFuncAttributeMaxDynamicSharedMemorySize, 70144);
    cudaFuncSetAttribute(score_kernel, cudaFuncAttributeMaxDynamicSharedMemorySize, 79872);

    setup_kernel<<<dim3(64, 4), 256, 70144>>>(cb, wk, wq);
    score_kernel<<<dim3(512, 4), 256, 79872>>>(latent, (float*)d_out);
    refine_kernel<<<512, 256>>>(latent, (float*)d_out);
}

// round 15
// speedup vs baseline: 1.3815x; 1.0230x over previous
#include <cuda_runtime.h>
#include <cstdint>

// ---------------------------------------------------------------------------
// QuantizerEncoder: 1-pass tf32 HMMA screen with raw-fp32 B operand
// (implicit tf32 truncation), cp.async-direct B tile, 32-bit-key argmax +
// ambiguity flags; flagged entries exactly recomputed in fp32.
//
//   score[code][px] = sum_d Mmat[code][d] * x[d][px]
//   out[n,h,w,m] = argmax_code score  (float-coded index)
// ---------------------------------------------------------------------------

typedef unsigned long long ULL;

__device__ float g_A[262144];             // tf32-hi (rounded), m16n8k8 A-frag layout
__device__ float g_MT[4 * 128 * 256];     // fp32 M^T [m][d][k] (refine)
__device__ int   g_cnt[4];                // flagged counts per m
__device__ int   g_list[4 * 65536];       // flagged pixel lists per m

// B-side truncated tf32: pair-diff sigma ~= 0.009 -> 0.075 is ~8.3 sigma
#define GAP_TH 0.075f

static __device__ __forceinline__ uint32_t f2tf32(float v) {
    uint32_t u;
    asm("cvt.rna.tf32.f32 %0, %1;" : "=r"(u) : "f"(v));
    return u;
}

static __device__ __forceinline__ uint32_t smem_u32(const void* p) {
    uint32_t a;
    asm("{ .reg .u64 t; cvta.to.shared.u64 t, %1; cvt.u32.u64 %0, t; }"
        : "=r"(a) : "l"(p));
    return a;
}

static __device__ __forceinline__ void mma8(float* d, float4 a, float2 b) {
    asm volatile(
        "mma.sync.aligned.m16n8k8.row.col.f32.tf32.tf32.f32 "
        "{%0,%1,%2,%3}, {%4,%5,%6,%7}, {%8,%9}, {%0,%1,%2,%3};"
        : "+f"(d[0]), "+f"(d[1]), "+f"(d[2]), "+f"(d[3])
        : "r"(__float_as_uint(a.x)), "r"(__float_as_uint(a.y)),
          "r"(__float_as_uint(a.z)), "r"(__float_as_uint(a.w)),
          "r"(__float_as_uint(b.x)), "r"(__float_as_uint(b.y)));
}

static __device__ __forceinline__ unsigned mono(float f) {
    unsigned u = __float_as_uint(f);
    return (u & 0x80000000u) ? ~u : (u | 0x80000000u);
}
static __device__ __forceinline__ float imono(unsigned u) {
    return (u & 0x80000000u) ? __uint_as_float(u & 0x7fffffffu)
                             : __uint_as_float(~u);
}

// ---------------- fused setup: keys (smem) -> Mmat -> g_A/g_MT --------------
// (round-13 measured-best config: grid (32,4), 8 k/block, 1 block/SM, 10.9us)
__global__ __launch_bounds__(256, 1)
void setup_kernel(const float* __restrict__ cb, const float* __restrict__ wk,
                  const float* __restrict__ wq) {
    extern __shared__ float sm[];
    float* skeys = sm + 16512;   // [8 k][128 c]
    float* scb   = sm + 17536;   // [8 k][128 d]
    const int m = blockIdx.y, kch = blockIdx.x, t = threadIdx.x;

    const float4* wk4 = (const float4*)(wk + (size_t)m * 16384);
#pragma unroll
    for (int i = 0; i < 16; i++) {
        int j = i * 256 + t, c = j >> 5, d4 = j & 31;
        float4 v = __ldg(wk4 + j);
        sm[(4 * d4 + 0) * 129 + c] = v.x;
        sm[(4 * d4 + 1) * 129 + c] = v.y;
        sm[(4 * d4 + 2) * 129 + c] = v.z;
        sm[(4 * d4 + 3) * 129 + c] = v.w;
    }
    ((float4*)scb)[t] = __ldg((const float4*)(cb + ((size_t)m * 256 + kch * 8) * 128) + t);
    __syncthreads();
    {
        int c = t & 127, b = t >> 7;       // k-locals b, b+2, b+4, b+6
        float s0 = 0.f, s1 = 0.f, s2 = 0.f, s3 = 0.f;
#pragma unroll 8
        for (int d = 0; d < 128; d++) {
            float w = sm[d * 129 + c];
            s0 += scb[(b + 0) * 128 + d] * w;   // warp-uniform scb -> broadcast
            s1 += scb[(b + 2) * 128 + d] * w;
            s2 += scb[(b + 4) * 128 + d] * w;
            s3 += scb[(b + 6) * 128 + d] * w;
        }
        skeys[(b + 0) * 128 + c] = s0;
        skeys[(b + 2) * 128 + c] = s1;
        skeys[(b + 4) * 128 + c] = s2;
        skeys[(b + 6) * 128 + c] = s3;
    }
    __syncthreads();

    const float4* wq4 = (const float4*)(wq + (size_t)m * 16384);
#pragma unroll
    for (int i = 0; i < 16; i++) ((float4*)sm)[i * 256 + t] = __ldg(wq4 + i * 256 + t);
    __syncthreads();
    {
        int d = t & 127, b = t >> 7;
        float v0 = 0.f, v1 = 0.f, v2 = 0.f, v3 = 0.f;
#pragma unroll 8
        for (int c = 0; c < 128; c++) {
            float w = sm[c * 128 + d];
            v0 += w * skeys[(b + 0) * 128 + c];
            v1 += w * skeys[(b + 2) * 128 + c];
            v2 += w * skeys[(b + 4) * 128 + c];
            v3 += w * skeys[(b + 6) * 128 + c];
        }
        float vals[4] = {v0, v1, v2, v3};
#pragma unroll
        for (int q = 0; q < 4; q++) {
            int kl = b + 2 * q;
            int k = kch * 8 + kl;
            float val = vals[q];
            g_MT[((size_t)m * 128 + d) * 256 + k] = val;

            uint32_t hib = f2tf32(val);
            int half_ = k >> 7, w = (k & 127) >> 4, r = k & 15;
            int ks = d >> 3, dc = d & 7;
            int ln, fi;
            if (r < 8) { ln = r * 4 + (dc & 3); fi = (dc >= 4) ? 2 : 0; }
            else       { ln = (r - 8) * 4 + (dc & 3); fi = (dc >= 4) ? 3 : 1; }
            size_t base = (size_t)(((m * 2 + half_) * 8 + w) * 16 + ks) * 128 + ln * 4 + fi;
            g_A[base] = __uint_as_float(hib);
        }
    }
    if (blockIdx.x == 0 && blockIdx.y == 0 && t < 4) g_cnt[t] = 0;
}

// ---------------- stage 1: raw-B tf32 screen + key32 argmax + flags ---------
// CTA: 256 threads, 128 px, one m. grid = (512, 4). 2 CTAs/SM.
// smem floats: [0,17408) B raw fp32 [128 d][136] (cp.async direct);
// gk32 u32[16][128] @17408 (8KB); gflag u8[16][128] @19456 (2KB). 79872 B.
__global__ __launch_bounds__(256, 2)
void score_kernel(const float* __restrict__ latent, float* __restrict__ out) {
    extern __shared__ float sb[];
    unsigned* gk32 = (unsigned*)(sb + 17408);
    unsigned char* gflag = (unsigned char*)(sb + 19456);

    const int t = threadIdx.x, lane = t & 31, wid = t >> 5;
    const int m = blockIdx.y;
    const int n = blockIdx.x >> 5;
    const int p0 = (blockIdx.x & 31) << 7;

    const float* xb = latent + ((size_t)(n * 512 + m * 128)) * 4096 + p0;
    const uint32_t bB = smem_u32(sb);

    // cp.async both halves straight into B[d][136] (raw fp32 == tf32-truncated
    // when consumed by HMMA). Group order: lo-d committed first.
#pragma unroll
    for (int i = 0; i < 8; i++) {
        int idx = i * 256 + t;             // d 0..63
        int d = idx >> 5, p4 = idx & 31;
        const float* src = xb + (size_t)d * 4096 + p4 * 4;
        asm volatile("cp.async.cg.shared.global [%0], [%1], 16;"
                     :: "r"(bB + (d * 136 + p4 * 4) * 4), "l"(src));
    }
    asm volatile("cp.async.commit_group;");
#pragma unroll
    for (int i = 8; i < 16; i++) {
        int idx = i * 256 + t;             // d 64..127
        int d = idx >> 5, p4 = idx & 31;
        const float* src = xb + (size_t)d * 4096 + p4 * 4;
        asm volatile("cp.async.cg.shared.global [%0], [%1], 16;"
                     :: "r"(bB + (d * 136 + p4 * 4) * 4), "l"(src));
    }
    asm volatile("cp.async.commit_group;");

    bool lo_ready = false, hi_ready = false;

    for (int half_ = 0; half_ < 2; half_++) {
        float acc[16][4];
#pragma unroll
        for (int j = 0; j < 16; j++)
#pragma unroll
            for (int c = 0; c < 4; c++) acc[j][c] = 0.f;

        const float4* pA = ((const float4*)g_A) +
                           (size_t)((m * 2 + half_) * 8 + wid) * 512;

        for (int kg = 0; kg < 2; kg++) {
            float4 afr[8];
#pragma unroll
            for (int ki = 0; ki < 8; ki++)
                afr[ki] = __ldg(pA + (kg * 8 + ki) * 32 + lane);

            if (kg == 0 && !lo_ready) {
                asm volatile("cp.async.wait_group 1;");
                __syncthreads();
                lo_ready = true;
            } else if (kg == 1 && !hi_ready) {
                asm volatile("cp.async.wait_group 0;");
                __syncthreads();
                hi_ready = true;
            }
#pragma unroll
            for (int ki = 0; ki < 8; ki++) {
                int ks = kg * 8 + ki;
                const float* bbase = sb + (ks * 8 + (lane & 3)) * 136 + (lane >> 2);
#pragma unroll
                for (int j = 0; j < 16; j++) {
                    float2 b = make_float2(bbase[j * 8], bbase[544 + j * 8]);
                    mma8(acc[j], afr[ki], b);
                }
            }
        }

        // ---- key32 argmax + ambiguity flag over this warp's 16 codes ----
        int r0 = half_ * 128 + wid * 16 + (lane >> 2);
        const unsigned gm = 0x11111111u << (lane & 3);
#pragma unroll
        for (int j = 0; j < 16; j++) {
#pragma unroll
            for (int cc = 0; cc < 2; cc++) {
                float v0 = acc[j][cc];        // code r0
                float v1 = acc[j][2 + cc];    // code r0+8
                unsigned k0 = (mono(v0) & 0xFFFFFF00u) | (unsigned)(255 - r0);
                unsigned k1 = (mono(v1) & 0xFFFFFF00u) | (unsigned)(255 - (r0 + 8));
                unsigned key = (k0 > k1) ? k0 : k1;
#pragma unroll
                for (int o = 4; o <= 16; o <<= 1) {
                    unsigned ok = __shfl_xor_sync(0xffffffffu, key, o);
                    if (ok > key) key = ok;
                }
                int wincode = 255 - (int)(key & 0xFFu);
                float thr = imono(key & 0xFFFFFF00u) - GAP_TH;
                int excess = ((v0 >= thr) && (wincode != r0)) +
                             ((v1 >= thr) && (wincode != r0 + 8));
                unsigned bal = __ballot_sync(0xffffffffu, excess > 0);
                if (lane < 4) {
                    int px = j * 8 + lane * 2 + cc;
                    gk32[(half_ * 8 + wid) * 128 + px] = key;
                    gflag[(half_ * 8 + wid) * 128 + px] =
                        ((bal & gm) != 0u) ? 1 : 0;
                }
            }
        }
    }
    __syncthreads();

    if (t < 128) {
        int px = t;
        unsigned best = 0, sec = 0;
        int g1 = 0;
#pragma unroll
        for (int g = 0; g < 16; g++) {
            unsigned k = gk32[g * 128 + px];
            if (k > best) { sec = best; best = k; g1 = g; }
            else if (k > sec) sec = k;
        }
        float f1 = imono(best & 0xFFFFFF00u);
        float f2 = imono(sec & 0xFFFFFF00u);
        int code = 255 - (int)(best & 0xFFu);
        int pix = n * 4096 + p0 + px;
        out[pix * 4 + m] = (float)code;
        bool flag = (gflag[g1 * 128 + px] != 0) || (f1 - f2 < GAP_TH);
        if (flag) {
            int pos = atomicAdd(&g_cnt[m], 1);
            g_list[m * 65536 + pos] = pix;
        }
    }
}

// ---------------- stage 2: batched exact fp32 refine (flattened) ------------
__global__ __launch_bounds__(256, 2)
void refine_kernel(const float* __restrict__ latent, float* __restrict__ out) {
    __shared__ float xs[128 * 32];     // [d][e]
    __shared__ ULL redk[32 * 64];      // [e][c4]
    __shared__ int spix[32];

    const int t = threadIdx.x;
    const int c0 = g_cnt[0], c1 = g_cnt[1], c2 = g_cnt[2], c3 = g_cnt[3];
    const int nb0 = (c0 + 31) >> 5, nb1 = (c1 + 31) >> 5;
    const int nb2 = (c2 + 31) >> 5, nb3 = (c3 + 31) >> 5;
    const int tot = nb0 + nb1 + nb2 + nb3;

    for (int jb = blockIdx.x; jb < tot; jb += gridDim.x) {
        int m, lb, cnt;
        if (jb < nb0)                  { m = 0; lb = jb; cnt = c0; }
        else if (jb < nb0 + nb1)       { m = 1; lb = jb - nb0; cnt = c1; }
        else if (jb < nb0 + nb1 + nb2) { m = 2; lb = jb - nb0 - nb1; cnt = c2; }
        else                           { m = 3; lb = jb - nb0 - nb1 - nb2; cnt = c3; }
        int ne = cnt - lb * 32;
        if (ne > 32) ne = 32;

        if (t < 32)
            spix[t] = g_list[m * 65536 + lb * 32 + ((t < ne) ? t : 0)];
        __syncthreads();

        {
            int e = t & 31, d0 = (t >> 5) * 16;
            int pp = spix[e];
            const float* xp = latent +
                ((size_t)((pp >> 12) * 512 + m * 128 + d0)) * 4096 + (pp & 4095);
            float v[16];
#pragma unroll
            for (int i = 0; i < 16; i++) v[i] = __ldg(xp + (size_t)i * 4096);
#pragma unroll
            for (int i = 0; i < 16; i++) xs[(d0 + i) * 32 + e] = v[i];
        }
        __syncthreads();

        const int c4 = t & 63, eg = t >> 6;
        float acc[4][8];
#pragma unroll
        for (int c = 0; c < 4; c++)
#pragma unroll
            for (int k = 0; k < 8; k++) acc[c][k] = 0.f;

        const float4* MT = (const float4*)(g_MT + (size_t)m * 32768);
#pragma unroll 8
        for (int d = 0; d < 128; d++) {
            float4 mv = __ldg(MT + d * 64 + c4);
            float4 xa = *(const float4*)(xs + d * 32 + eg * 8);
            float4 xc = *(const float4*)(xs + d * 32 + eg * 8 + 4);
            float xv[8] = {xa.x, xa.y, xa.z, xa.w, xc.x, xc.y, xc.z, xc.w};
#pragma unroll
            for (int k = 0; k < 8; k++) {
                acc[0][k] += mv.x * xv[k];
                acc[1][k] += mv.y * xv[k];
                acc[2][k] += mv.z * xv[k];
                acc[3][k] += mv.w * xv[k];
            }
        }

#pragma unroll
        for (int k = 0; k < 8; k++) {
            ULL key = 0;
#pragma unroll
            for (int c = 0; c < 4; c++) {
                int code = c4 * 4 + c;
                ULL kk = ((ULL)mono(acc[c][k]) << 32) | (unsigned)(255 - code);
                if (kk > key) key = kk;
            }
            redk[(eg * 8 + k) * 64 + c4] = key;
        }
        __syncthreads();

        {
            int e2 = t >> 3, ch = t & 7;
            ULL best = redk[e2 * 64 + ch * 8];
#pragma unroll
            for (int q = 1; q < 8; q++) {
                ULL o = redk[e2 * 64 + ch * 8 + q];
                if (o > best) best = o;
            }
#pragma unroll
            for (int o = 1; o < 8; o <<= 1) {
                ULL ob = __shfl_xor_sync(0xffffffffu, best, o);
                if (ob > best) best = ob;
            }
            if (ch == 0 && e2 < ne)
                out[spix[e2] * 4 + m] = (float)(255 - (int)(best & 0xFF));
        }
        __syncthreads();
    }
}

extern "C" void kernel_launch(void* const* d_in, const int* in_sizes, int n_in,
                              void* d_out, int out_size) {
    const float* latent = (const float*)d_in[0];
    const float* cb     = (const float*)d_in[1];
    const float* wq     = (const float*)d_in[2];
    const float* wk     = (const float*)d_in[3];

    cudaFuncSetAttribute(setup_kernel, cudaFuncAttributeMaxDynamicSharedMemorySize, 74240);
    cudaFuncSetAttribute(score_kernel, cudaFuncAttributeMaxDynamicSharedMemorySize, 79872);

    setup_kernel<<<dim3(32, 4), 256, 74240>>>(cb, wk, wq);
    score_kernel<<<dim3(512, 4), 256, 79872>>>(latent, (float*)d_out);
    refine_kernel<<<512, 256>>>(latent, (float*)d_out);
}